// round 12
// baseline (speedup 1.0000x reference)
#include <cuda_runtime.h>
#include <cstdint>
#include <math.h>

// ---------------- problem constants ----------------
#define BSZ   8192
#define IN_D  2048
#define H_D   2048
#define CAT_D 4096

// ---------------- GEMM tile config ----------------
#define BM 128
#define BN 128
#define BK 32
#define LDSW 36            // BK + 4 pad (floats)
#define NT 256

// ---------------- tf32-rounded scratch ----------------
__device__ float g_cvt_in[(size_t)BSZ * IN_D];
__device__ float g_cvt_st[(size_t)BSZ * H_D];
__device__ float g_cvt_gw[(size_t)H_D * CAT_D];
__device__ float g_cvt_wi[(size_t)H_D * IN_D];

// ---------------- helpers ----------------
__device__ __forceinline__ uint32_t smem_u32(const void* p) {
    uint32_t a;
    asm("{ .reg .u64 t; cvta.to.shared.u64 t, %1; cvt.u32.u64 %0, t; }" : "=r"(a) : "l"(p));
    return a;
}
__device__ __forceinline__ void cp16(uint32_t dst, const void* src) {
    asm volatile("cp.async.cg.shared.global [%0], [%1], 16;" :: "r"(dst), "l"(src) : "memory");
}
#define CP_COMMIT() asm volatile("cp.async.commit_group;" ::: "memory")
#define CP_WAIT0()  asm volatile("cp.async.wait_group 0;" ::: "memory")

__device__ __forceinline__ void mma8(float* d, const uint32_t* a, const uint32_t* b) {
    asm volatile(
        "mma.sync.aligned.m16n8k8.row.col.f32.tf32.tf32.f32 "
        "{%0,%1,%2,%3}, {%4,%5,%6,%7}, {%8,%9}, {%0,%1,%2,%3};"
        : "+f"(d[0]), "+f"(d[1]), "+f"(d[2]), "+f"(d[3])
        : "r"(a[0]), "r"(a[1]), "r"(a[2]), "r"(a[3]), "r"(b[0]), "r"(b[1]));
}

// ---------------- fused prep: tf32-round all 4 tensors + concat ----------------
// seg sizes in float4 units
#define N4_IN  ((size_t)BSZ * IN_D / 4)
#define N4_ST  ((size_t)BSZ * H_D / 4)
#define N4_GW  ((size_t)H_D * CAT_D / 4)
#define N4_WI  ((size_t)H_D * IN_D / 4)
#define N4_TOT (N4_IN + N4_ST + N4_GW + N4_WI)

__device__ __forceinline__ float4 round4(float4 v) {
    uint32_t a, b, c, d;
    asm("cvt.rna.tf32.f32 %0, %1;" : "=r"(a) : "f"(v.x));
    asm("cvt.rna.tf32.f32 %0, %1;" : "=r"(b) : "f"(v.y));
    asm("cvt.rna.tf32.f32 %0, %1;" : "=r"(c) : "f"(v.z));
    asm("cvt.rna.tf32.f32 %0, %1;" : "=r"(d) : "f"(v.w));
    float4 o;
    o.x = __uint_as_float(a); o.y = __uint_as_float(b);
    o.z = __uint_as_float(c); o.w = __uint_as_float(d);
    return o;
}

__global__ void prep_kernel(const float4* __restrict__ input,
                            const float4* __restrict__ state,
                            const float4* __restrict__ gw,
                            const float4* __restrict__ wi,
                            float4* __restrict__ concat_out)
{
    const int C4_IN = IN_D / 4;
    const int C4_CAT = CAT_D / 4;
    for (size_t i = (size_t)blockIdx.x * blockDim.x + threadIdx.x;
         i < N4_TOT; i += (size_t)gridDim.x * blockDim.x) {
        if (i < N4_IN) {
            float4 v = input[i];
            size_t b = i / C4_IN; int c = (int)(i % C4_IN);
            concat_out[b * C4_CAT + c] = v;
            ((float4*)g_cvt_in)[i] = round4(v);
        } else if (i < N4_IN + N4_ST) {
            size_t j = i - N4_IN;
            float4 v = state[j];
            size_t b = j / C4_IN; int c = (int)(j % C4_IN);
            concat_out[b * C4_CAT + C4_IN + c] = v;
            ((float4*)g_cvt_st)[j] = round4(v);
        } else if (i < N4_IN + N4_ST + N4_GW) {
            size_t j = i - N4_IN - N4_ST;
            ((float4*)g_cvt_gw)[j] = round4(gw[j]);
        } else {
            size_t j = i - N4_IN - N4_ST - N4_GW;
            ((float4*)g_cvt_wi)[j] = round4(wi[j]);
        }
    }
}

// ---------------- fused GEMM ----------------
// smem per stage: A + Bg + Bv = 3 * 128 * 36 floats = 55296 B; x2 stages
#define STG_F (3 * BM * LDSW)

template<bool VAL>
__device__ __forceinline__ void load_stage(float* stage, int blockM, int blockN, int c, int tid)
{
    const int row = tid >> 1;
    const int u0 = (tid & 1) * 4;

    const bool ph_in = (c < 64);
    const int k0 = ph_in ? c * BK : (c - 64) * BK;
    const float* asrc = (ph_in ? g_cvt_in : g_cvt_st) + (size_t)(blockM + row) * 2048 + k0;
    const int kg = ph_in ? k0 : IN_D + k0;
    const float* gsrc = g_cvt_gw + (size_t)(blockN + row) * CAT_D + kg;

    uint32_t adst = smem_u32(stage + (size_t)row * LDSW);
    uint32_t gdst = smem_u32(stage + (size_t)(BM * LDSW) + (size_t)row * LDSW);
#pragma unroll
    for (int j = 0; j < 4; j++) {
        const int u = u0 + j;
        cp16(adst + (uint32_t)u * 16, asrc + u * 4);
        cp16(gdst + (uint32_t)u * 16, gsrc + u * 4);
    }
    if (VAL) {
        const float* vsrc = g_cvt_wi + (size_t)(blockN + row) * IN_D + k0;
        uint32_t vdst = smem_u32(stage + (size_t)(2 * BM * LDSW) + (size_t)row * LDSW);
#pragma unroll
        for (int j = 0; j < 4; j++) {
            const int u = u0 + j;
            cp16(vdst + (uint32_t)u * 16, vsrc + u * 4);
        }
    }
}

// Output layout (floats): new_h | concat | pre_gate | gate | values | pre_h
__global__ __launch_bounds__(NT, 1)
void fused_gemm_kernel(const float* __restrict__ state,
                       const float* __restrict__ bias,
                       float* __restrict__ out)
{
    extern __shared__ float sm[];
    const int tid = threadIdx.x;
    const int wid = tid >> 5, lane = tid & 31;
    const int g = lane >> 2, tig = lane & 3;
    const int m0 = (wid >> 2) * 64;
    const int n0 = (wid & 3) * 32;
    const int blockM = blockIdx.y * BM;
    const int blockN = blockIdx.x * BN;

    float* S0 = sm;
    float* S1 = sm + STG_F;

    float acc_g[4][4][4];
    float acc_v[4][4][4];
#pragma unroll
    for (int i = 0; i < 4; i++)
#pragma unroll
        for (int j = 0; j < 4; j++)
#pragma unroll
            for (int t = 0; t < 4; t++) { acc_g[i][j][t] = 0.f; acc_v[i][j][t] = 0.f; }

    load_stage<true>(S0, blockM, blockN, 0, tid);
    CP_COMMIT();

    for (int c = 0; c < 128; c++) {
        CP_WAIT0();
        __syncthreads();
        if (c + 1 < 128) {
            float* nxt = (c & 1) ? S0 : S1;
            if (c + 1 < 64) load_stage<true>(nxt, blockM, blockN, c + 1, tid);
            else            load_stage<false>(nxt, blockM, blockN, c + 1, tid);
            CP_COMMIT();
        }
        float* cur = (c & 1) ? S1 : S0;
        const float* smA = cur;
        const float* smG = cur + BM * LDSW;
        const float* smV = cur + 2 * BM * LDSW;
        const bool ph_in = (c < 64);

#pragma unroll
        for (int kk = 0; kk < 4; kk++) {
            uint32_t af[4][4], bg[4][2];
#pragma unroll
            for (int i = 0; i < 4; i++) {
                const float* base = smA + (size_t)(m0 + i * 16 + g) * LDSW + kk * 8 + tig;
                af[i][0] = __float_as_uint(base[0]);
                af[i][1] = __float_as_uint(base[8 * LDSW]);
                af[i][2] = __float_as_uint(base[4]);
                af[i][3] = __float_as_uint(base[8 * LDSW + 4]);
            }
#pragma unroll
            for (int j = 0; j < 4; j++) {
                const float* base = smG + (size_t)(n0 + j * 8 + g) * LDSW + kk * 8 + tig;
                bg[j][0] = __float_as_uint(base[0]);
                bg[j][1] = __float_as_uint(base[4]);
            }
#pragma unroll
            for (int i = 0; i < 4; i++)
#pragma unroll
                for (int j = 0; j < 4; j++)
                    mma8(acc_g[i][j], af[i], bg[j]);

            if (ph_in) {
                uint32_t bv[4][2];
#pragma unroll
                for (int j = 0; j < 4; j++) {
                    const float* base = smV + (size_t)(n0 + j * 8 + g) * LDSW + kk * 8 + tig;
                    bv[j][0] = __float_as_uint(base[0]);
                    bv[j][1] = __float_as_uint(base[4]);
                }
#pragma unroll
                for (int i = 0; i < 4; i++)
#pragma unroll
                    for (int j = 0; j < 4; j++)
                        mma8(acc_v[i][j], af[i], bv[j]);
            }
        }
    }

    // ---------------- fully fused epilogue ----------------
    const size_t BH = (size_t)BSZ * H_D;
    const size_t BC = (size_t)BSZ * CAT_D;
    float* out_newh = out;
    float* out_pg   = out + BH + BC;
    float* out_gt   = out_pg + BH;
    float* out_val  = out_gt + BH;
    float* out_ph   = out_val + BH;

#pragma unroll
    for (int i = 0; i < 4; i++) {
        const int r0 = blockM + m0 + i * 16 + g;
#pragma unroll
        for (int j = 0; j < 4; j++) {
            const int c = blockN + n0 + j * 8 + tig * 2;
            const float b0 = bias[c], b1 = bias[c + 1];
            const size_t o0 = (size_t)r0 * H_D + c;
            const size_t o1 = (size_t)(r0 + 8) * H_D + c;
            float2 sa = *(const float2*)(state + o0);
            float2 sb = *(const float2*)(state + o1);

            float pg0 = acc_g[i][j][0] + b0, pg1 = acc_g[i][j][1] + b1;
            float pg2 = acc_g[i][j][2] + b0, pg3 = acc_g[i][j][3] + b1;
            float g0 = fminf(fmaxf(pg0, 0.f), 1.f), g1 = fminf(fmaxf(pg1, 0.f), 1.f);
            float g2 = fminf(fmaxf(pg2, 0.f), 1.f), g3 = fminf(fmaxf(pg3, 0.f), 1.f);
            float v0 = tanhf(acc_v[i][j][0]), v1 = tanhf(acc_v[i][j][1]);
            float v2 = tanhf(acc_v[i][j][2]), v3 = tanhf(acc_v[i][j][3]);
            float ph0 = sa.x * (1.f - g0) + v0 * g0;
            float ph1 = sa.y * (1.f - g1) + v1 * g1;
            float ph2 = sb.x * (1.f - g2) + v2 * g2;
            float ph3 = sb.y * (1.f - g3) + v3 * g3;

            *(float2*)(out_pg + o0) = make_float2(pg0, pg1);
            *(float2*)(out_pg + o1) = make_float2(pg2, pg3);
            *(float2*)(out_gt + o0) = make_float2(g0, g1);
            *(float2*)(out_gt + o1) = make_float2(g2, g3);
            *(float2*)(out_val + o0) = make_float2(v0, v1);
            *(float2*)(out_val + o1) = make_float2(v2, v3);
            *(float2*)(out_ph + o0) = make_float2(ph0, ph1);
            *(float2*)(out_ph + o1) = make_float2(ph2, ph3);
            *(float2*)(out_newh + o0) = make_float2(fmaxf(ph0, 0.f), fmaxf(ph1, 0.f));
            *(float2*)(out_newh + o1) = make_float2(fmaxf(ph2, 0.f), fmaxf(ph3, 0.f));
        }
    }
}

extern "C" void kernel_launch(void* const* d_in, const int* in_sizes, int n_in,
                              void* d_out, int out_size)
{
    const float* input = (const float*)d_in[0];
    const float* state = (const float*)d_in[1];
    const float* gw    = (const float*)d_in[2];
    const float* bias  = (const float*)d_in[3];
    const float* wi    = (const float*)d_in[4];
    float* out = (float*)d_out;

    const size_t BH = (size_t)BSZ * H_D;
    float* concat_out = out + BH;

    prep_kernel<<<2048, 256>>>((const float4*)input, (const float4*)state,
                               (const float4*)gw, (const float4*)wi,
                               (float4*)concat_out);

    const int smem_bytes = 2 * STG_F * sizeof(float);   // 110592
    cudaFuncSetAttribute(fused_gemm_kernel, cudaFuncAttributeMaxDynamicSharedMemorySize, smem_bytes);

    dim3 grid(H_D / BN, BSZ / BM);   // (16, 64)
    fused_gemm_kernel<<<grid, NT, smem_bytes>>>(state, bias, out);
}

// round 13
// speedup vs baseline: 1.2103x; 1.2103x over previous
#include <cuda_runtime.h>
#include <cstdint>
#include <math.h>

// ---------------- problem constants ----------------
#define BSZ   8192
#define IN_D  2048
#define H_D   2048
#define CAT_D 4096

// ---------------- GEMM tile config ----------------
#define BM 128
#define BN 128
#define BK 32
#define LDSW 36            // BK + 4 pad (floats); 144B = 9*16B row stride
#define NT 256

// ---------------- tf32-rounded scratch ----------------
__device__ float g_cvt_in[(size_t)BSZ * IN_D];
__device__ float g_cvt_st[(size_t)BSZ * H_D];
__device__ float g_cvt_gw[(size_t)H_D * CAT_D];
__device__ float g_cvt_wi[(size_t)H_D * IN_D];

// ---------------- helpers ----------------
__device__ __forceinline__ uint32_t smem_u32(const void* p) {
    uint32_t a;
    asm("{ .reg .u64 t; cvta.to.shared.u64 t, %1; cvt.u32.u64 %0, t; }" : "=r"(a) : "l"(p));
    return a;
}
__device__ __forceinline__ void cp16(uint32_t dst, const void* src) {
    asm volatile("cp.async.cg.shared.global [%0], [%1], 16;" :: "r"(dst), "l"(src) : "memory");
}
#define CP_COMMIT() asm volatile("cp.async.commit_group;" ::: "memory")
#define CP_WAIT0()  asm volatile("cp.async.wait_group 0;" ::: "memory")

__device__ __forceinline__ void mma8(float* d, const uint32_t* a, const uint32_t* b) {
    asm volatile(
        "mma.sync.aligned.m16n8k8.row.col.f32.tf32.tf32.f32 "
        "{%0,%1,%2,%3}, {%4,%5,%6,%7}, {%8,%9}, {%0,%1,%2,%3};"
        : "+f"(d[0]), "+f"(d[1]), "+f"(d[2]), "+f"(d[3])
        : "r"(a[0]), "r"(a[1]), "r"(a[2]), "r"(a[3]), "r"(b[0]), "r"(b[1]));
}

// ldmatrix x4: loads 4 8x8-b16 matrices (= 4 8x4-b32), one b32 per thread per matrix
__device__ __forceinline__ void ldsm4(uint32_t* r, uint32_t a) {
    asm volatile("ldmatrix.sync.aligned.m8n8.x4.shared.b16 {%0,%1,%2,%3}, [%4];"
                 : "=r"(r[0]), "=r"(r[1]), "=r"(r[2]), "=r"(r[3]) : "r"(a));
}

// ---------------- fused prep: tf32-round all 4 tensors + concat ----------------
#define N4_IN  ((size_t)BSZ * IN_D / 4)
#define N4_ST  ((size_t)BSZ * H_D / 4)
#define N4_GW  ((size_t)H_D * CAT_D / 4)
#define N4_WI  ((size_t)H_D * IN_D / 4)
#define N4_TOT (N4_IN + N4_ST + N4_GW + N4_WI)

__device__ __forceinline__ float4 round4(float4 v) {
    uint32_t a, b, c, d;
    asm("cvt.rna.tf32.f32 %0, %1;" : "=r"(a) : "f"(v.x));
    asm("cvt.rna.tf32.f32 %0, %1;" : "=r"(b) : "f"(v.y));
    asm("cvt.rna.tf32.f32 %0, %1;" : "=r"(c) : "f"(v.z));
    asm("cvt.rna.tf32.f32 %0, %1;" : "=r"(d) : "f"(v.w));
    float4 o;
    o.x = __uint_as_float(a); o.y = __uint_as_float(b);
    o.z = __uint_as_float(c); o.w = __uint_as_float(d);
    return o;
}

__global__ void prep_kernel(const float4* __restrict__ input,
                            const float4* __restrict__ state,
                            const float4* __restrict__ gw,
                            const float4* __restrict__ wi,
                            float4* __restrict__ concat_out)
{
    const int C4_IN = IN_D / 4;
    const int C4_CAT = CAT_D / 4;
    for (size_t i = (size_t)blockIdx.x * blockDim.x + threadIdx.x;
         i < N4_TOT; i += (size_t)gridDim.x * blockDim.x) {
        if (i < N4_IN) {
            float4 v = input[i];
            size_t b = i / C4_IN; int c = (int)(i % C4_IN);
            concat_out[b * C4_CAT + c] = v;
            ((float4*)g_cvt_in)[i] = round4(v);
        } else if (i < N4_IN + N4_ST) {
            size_t j = i - N4_IN;
            float4 v = state[j];
            size_t b = j / C4_IN; int c = (int)(j % C4_IN);
            concat_out[b * C4_CAT + C4_IN + c] = v;
            ((float4*)g_cvt_st)[j] = round4(v);
        } else if (i < N4_IN + N4_ST + N4_GW) {
            size_t j = i - N4_IN - N4_ST;
            ((float4*)g_cvt_gw)[j] = round4(gw[j]);
        } else {
            size_t j = i - N4_IN - N4_ST - N4_GW;
            ((float4*)g_cvt_wi)[j] = round4(wi[j]);
        }
    }
}

// ---------------- stage loader ----------------
template<bool GATE>
__device__ __forceinline__ void load_stage(float* smA, float* smB,
        const float* __restrict__ W, int blockM, int blockN, int k0, int tid)
{
    const int row = tid >> 1;          // 0..127
    const int u0 = (tid & 1) * 4;      // 16B units

    const float* Aptr = g_cvt_in;
    int ka = k0;
    if (GATE && k0 >= IN_D) { Aptr = g_cvt_st; ka = k0 - IN_D; }
    const float* asrc = Aptr + (size_t)(blockM + row) * 2048 + ka;
    const size_t bld = GATE ? (size_t)CAT_D : (size_t)IN_D;
    const float* bsrc = W + (size_t)(blockN + row) * bld + k0;

    uint32_t adst = smem_u32(smA + (size_t)row * LDSW);
    uint32_t bdst = smem_u32(smB + (size_t)row * LDSW);
#pragma unroll
    for (int j = 0; j < 4; j++) {
        const int u = u0 + j;
        cp16(adst + (uint32_t)u * 16, asrc + u * 4);
        cp16(bdst + (uint32_t)u * 16, bsrc + u * 4);
    }
}

// ---------------- stage compute via ldmatrix: warp tile 64x32 ----------------
__device__ __forceinline__ void compute_stage(const float* smA, const float* smB,
        float acc[4][4][4], int m0, int n0, int lane)
{
    // A addresses: lanes 0-15 -> rows 0-15 @ k0; lanes 16-31 -> rows 0-15 @ k4
    uint32_t aaddr = smem_u32(smA + (size_t)(m0 + (lane & 15)) * LDSW + ((lane >> 4) * 4));
    // B addresses: matrices = {n0-7@k0, n0-7@k4, n8-15@k0, n8-15@k4}
    uint32_t baddr = smem_u32(smB + (size_t)(n0 + (lane & 7) + ((lane >> 4) & 1) * 8) * LDSW
                              + (((lane >> 3) & 1) * 4));
#pragma unroll
    for (int kk = 0; kk < 4; kk++) {
        uint32_t af[4][4], bf[2][4];
#pragma unroll
        for (int i = 0; i < 4; i++)
            ldsm4(af[i], aaddr + (uint32_t)(i * 16 * LDSW * 4) + (uint32_t)(kk * 32));
#pragma unroll
        for (int jj = 0; jj < 2; jj++)
            ldsm4(bf[jj], baddr + (uint32_t)(jj * 16 * LDSW * 4) + (uint32_t)(kk * 32));
        // bf[jj] = { b[2jj][0], b[2jj][1], b[2jj+1][0], b[2jj+1][1] }
#pragma unroll
        for (int i = 0; i < 4; i++)
#pragma unroll
            for (int j = 0; j < 4; j++)
                mma8(acc[i][j], af[i], &bf[j >> 1][(j & 1) * 2]);
    }
}

// Output layout (floats): new_h | concat | pre_gate | gate | values | pre_h
template<bool GATE>
__global__ __launch_bounds__(NT, 2)
void gemm_kernel(const float* __restrict__ state,
                 const float* __restrict__ W, const float* __restrict__ bias,
                 float* __restrict__ out)
{
    extern __shared__ float sm[];
    const int tid = threadIdx.x;
    const int wid = tid >> 5, lane = tid & 31;
    const int g = lane >> 2, tig = lane & 3;
    const int m0 = (wid >> 2) * 64;    // 0 or 64
    const int n0 = (wid & 3) * 32;     // 0..96
    const int blockM = blockIdx.y * BM;
    const int blockN = blockIdx.x * BN;

    const int KT = (GATE ? CAT_D : IN_D) / BK;

    float* A0 = sm;
    float* B0 = sm + BM * LDSW;
    float* A1 = sm + (BM + BN) * LDSW;
    float* B1 = A1 + BM * LDSW;

    float acc[4][4][4];
#pragma unroll
    for (int i = 0; i < 4; i++)
#pragma unroll
        for (int j = 0; j < 4; j++)
#pragma unroll
            for (int t = 0; t < 4; t++) acc[i][j][t] = 0.f;

    load_stage<GATE>(A0, B0, W, blockM, blockN, 0, tid);
    CP_COMMIT();

    // single-sync pipeline: wait -> sync -> issue next load -> compute
    for (int kt = 0; kt < KT; kt++) {
        CP_WAIT0();
        __syncthreads();
        if (kt + 1 < KT) {
            float* nA = (kt & 1) ? A0 : A1;
            float* nB = (kt & 1) ? B0 : B1;
            load_stage<GATE>(nA, nB, W, blockM, blockN, (kt + 1) * BK, tid);
            CP_COMMIT();
        }
        float* cA = (kt & 1) ? A1 : A0;
        float* cB = (kt & 1) ? B1 : B0;
        compute_stage(cA, cB, acc, m0, n0, lane);
    }

    // ---------------- fused epilogue ----------------
    const size_t BH = (size_t)BSZ * H_D;
    const size_t BC = (size_t)BSZ * CAT_D;

    if (GATE) {
        float* out_pg = out + BH + BC;
        float* out_gt = out_pg + BH;
#pragma unroll
        for (int i = 0; i < 4; i++) {
            const int r0 = blockM + m0 + i * 16 + g;
#pragma unroll
            for (int j = 0; j < 4; j++) {
                const int c = blockN + n0 + j * 8 + tig * 2;
                const float b0 = bias[c], b1 = bias[c + 1];
                float pg0 = acc[i][j][0] + b0, pg1 = acc[i][j][1] + b1;
                float pg2 = acc[i][j][2] + b0, pg3 = acc[i][j][3] + b1;
                const size_t o0 = (size_t)r0 * H_D + c;
                const size_t o1 = (size_t)(r0 + 8) * H_D + c;
                *(float2*)(out_pg + o0) = make_float2(pg0, pg1);
                *(float2*)(out_pg + o1) = make_float2(pg2, pg3);
                *(float2*)(out_gt + o0) = make_float2(fminf(fmaxf(pg0, 0.f), 1.f),
                                                      fminf(fmaxf(pg1, 0.f), 1.f));
                *(float2*)(out_gt + o1) = make_float2(fminf(fmaxf(pg2, 0.f), 1.f),
                                                      fminf(fmaxf(pg3, 0.f), 1.f));
            }
        }
    } else {
        // value kernel runs AFTER gate kernel: gate region of out is final.
        float* out_newh = out;
        float* out_gt   = out + 2 * BH + BC;
        float* out_val  = out + 3 * BH + BC;
        float* out_ph   = out + 4 * BH + BC;
#pragma unroll
        for (int i = 0; i < 4; i++) {
            const int r0 = blockM + m0 + i * 16 + g;
#pragma unroll
            for (int j = 0; j < 4; j++) {
                const int c = blockN + n0 + j * 8 + tig * 2;
                const size_t o0 = (size_t)r0 * H_D + c;
                const size_t o1 = (size_t)(r0 + 8) * H_D + c;
                float v0 = tanhf(acc[i][j][0]), v1 = tanhf(acc[i][j][1]);
                float v2 = tanhf(acc[i][j][2]), v3 = tanhf(acc[i][j][3]);
                float2 ga = *(const float2*)(out_gt + o0);
                float2 gb = *(const float2*)(out_gt + o1);
                float2 sa = *(const float2*)(state + o0);
                float2 sb = *(const float2*)(state + o1);
                float ph0 = sa.x * (1.f - ga.x) + v0 * ga.x;
                float ph1 = sa.y * (1.f - ga.y) + v1 * ga.y;
                float ph2 = sb.x * (1.f - gb.x) + v2 * gb.x;
                float ph3 = sb.y * (1.f - gb.y) + v3 * gb.y;
                *(float2*)(out_val + o0) = make_float2(v0, v1);
                *(float2*)(out_val + o1) = make_float2(v2, v3);
                *(float2*)(out_ph + o0) = make_float2(ph0, ph1);
                *(float2*)(out_ph + o1) = make_float2(ph2, ph3);
                *(float2*)(out_newh + o0) = make_float2(fmaxf(ph0, 0.f), fmaxf(ph1, 0.f));
                *(float2*)(out_newh + o1) = make_float2(fmaxf(ph2, 0.f), fmaxf(ph3, 0.f));
            }
        }
    }
}

extern "C" void kernel_launch(void* const* d_in, const int* in_sizes, int n_in,
                              void* d_out, int out_size)
{
    const float* input = (const float*)d_in[0];
    const float* state = (const float*)d_in[1];
    const float* gw    = (const float*)d_in[2];
    const float* bias  = (const float*)d_in[3];
    const float* wi    = (const float*)d_in[4];
    float* out = (float*)d_out;

    const size_t BH = (size_t)BSZ * H_D;
    float* concat_out = out + BH;

    // single prep kernel: tf32-round all operands + write concat region
    prep_kernel<<<2048, 256>>>((const float4*)input, (const float4*)state,
                               (const float4*)gw, (const float4*)wi,
                               (float4*)concat_out);

    const int smem_bytes = 2 * (BM + BN) * LDSW * sizeof(float);   // 73728
    cudaFuncSetAttribute(gemm_kernel<true>,  cudaFuncAttributeMaxDynamicSharedMemorySize, smem_bytes);
    cudaFuncSetAttribute(gemm_kernel<false>, cudaFuncAttributeMaxDynamicSharedMemorySize, smem_bytes);

    dim3 grid(H_D / BN, BSZ / BM);   // (16, 64)
    gemm_kernel<true><<<grid, NT, smem_bytes>>>(state, gw, bias, out);
    gemm_kernel<false><<<grid, NT, smem_bytes>>>(state, wi, bias, out);
}